// round 2
// baseline (speedup 1.0000x reference)
#include <cuda_runtime.h>
#include <math.h>

#define B_ 4
#define N_ 4096
#define DIN_ 256
#define DOUT_ 128
#define NW_ (N_/32)

#define LUT_N 4096
// domain [-56, 56], step = 112/4096; index = s*LUT_INV + LUT_OFF
#define LUT_INV (36.571428571428571f)   /* 4096/112 */
#define LUT_OFF 2048.0f
#define MAXTF 4094.999f

__device__ float    g_h[B_*N_*DOUT_];
__device__ float    g_w1[B_*N_];
__device__ float    g_w2[B_*N_];
__device__ float    g_invS[B_*N_];
__device__ unsigned g_mask[(size_t)B_*N_*NW_];
__device__ float2   g_lut[LUT_N];
__device__ float    g_part[B_*32*DOUT_];

// ---------- packed fp32x2 helpers (sm_103a FFMA2) ----------
__device__ __forceinline__ unsigned long long packf2(float lo, float hi){
    unsigned long long r;
    asm("mov.b64 %0, {%1,%2};" : "=l"(r) : "f"(lo), "f"(hi));
    return r;
}
__device__ __forceinline__ float2 unpackf2(unsigned long long v){
    float2 r;
    asm("mov.b64 {%0,%1}, %2;" : "=f"(r.x), "=f"(r.y) : "l"(v));
    return r;
}
__device__ __forceinline__ unsigned long long ffma2(unsigned long long a, unsigned long long b, unsigned long long c){
    unsigned long long d;
    asm("fma.rn.f32x2 %0, %1, %2, %3;" : "=l"(d) : "l"(a), "l"(b), "l"(c));
    return d;
}

// ---------- pack adj -> bitmask (warp ballot, fully coalesced) ----------
__global__ __launch_bounds__(256) void k_pack(const int* __restrict__ adj){
    int warp_global = (blockIdx.x*blockDim.x + threadIdx.x) >> 5;
    int lane = threadIdx.x & 31;
    const int* p = adj + (size_t)warp_global * 1024;
    unsigned my = 0;
    #pragma unroll
    for (int w = 0; w < 32; w++){
        int v = p[w*32 + lane];
        unsigned m = __ballot_sync(0xffffffffu, v > 0);
        if (lane == w) my = m;
    }
    g_mask[(size_t)warp_global*32 + lane] = my;
}

// ---------- LUT: G(s) = exp(gelu(s)) ----------
__global__ void k_lut(){
    int k = blockIdx.x*256 + threadIdx.x;
    if (k >= LUT_N) return;
    double step = 112.0/4096.0;
    double x0 = -56.0 + k*step;
    double x1 = x0 + step;
    double g0 = 0.5*x0*(1.0 + erf(x0*0.70710678118654752440));
    double g1 = 0.5*x1*(1.0 + erf(x1*0.70710678118654752440));
    float v0 = (float)exp(g0);
    float v1 = (float)exp(g1);
    g_lut[k] = make_float2(v0, v1 - v0);
}

// ---------- h = x @ W  (M=16384, N=128, K=256), f32x2 ----------
__global__ __launch_bounds__(256) void k_h(const float* __restrict__ x, const float* __restrict__ w){
    __shared__ float As[32*128];
    __shared__ float Bs[32*128];
    int m0 = blockIdx.x * 128;
    int ig = threadIdx.x >> 4;   // 0..15
    int dg = threadIdx.x & 15;   // 0..15
    int i0 = ig*8, d0 = dg*8;
    unsigned long long acc[8][4] = {};
    for (int kb = 0; kb < DIN_; kb += 32){
        __syncthreads();
        {
            int r  = threadIdx.x >> 1;
            int kh = (threadIdx.x & 1)*16;
            const float4* src = (const float4*)(x + (size_t)(m0+r)*DIN_ + kb + kh);
            #pragma unroll
            for (int q = 0; q < 4; q++){
                float4 v = src[q];
                int kc = kh + q*4;
                As[(kc+0)*128 + r] = v.x;
                As[(kc+1)*128 + r] = v.y;
                As[(kc+2)*128 + r] = v.z;
                As[(kc+3)*128 + r] = v.w;
            }
            int kk = threadIdx.x >> 3;
            int c  = (threadIdx.x & 7)*16;
            const float4* bsrc = (const float4*)(w + (size_t)(kb+kk)*DOUT_ + c);
            float4* bdst = (float4*)(Bs + kk*128 + c);
            #pragma unroll
            for (int q = 0; q < 4; q++) bdst[q] = bsrc[q];
        }
        __syncthreads();
        #pragma unroll 8
        for (int kk = 0; kk < 32; kk++){
            float4 a0 = *(const float4*)(As + kk*128 + i0);
            float4 a1 = *(const float4*)(As + kk*128 + i0 + 4);
            float4 b0 = *(const float4*)(Bs + kk*128 + d0);
            float4 b1 = *(const float4*)(Bs + kk*128 + d0 + 4);
            unsigned long long bp[4] = { packf2(b0.x,b0.y), packf2(b0.z,b0.w),
                                         packf2(b1.x,b1.y), packf2(b1.z,b1.w) };
            float aa[8] = {a0.x,a0.y,a0.z,a0.w,a1.x,a1.y,a1.z,a1.w};
            #pragma unroll
            for (int r = 0; r < 8; r++){
                unsigned long long ap = packf2(aa[r], aa[r]);
                #pragma unroll
                for (int p = 0; p < 4; p++) acc[r][p] = ffma2(ap, bp[p], acc[r][p]);
            }
        }
    }
    #pragma unroll
    for (int r = 0; r < 8; r++){
        float2 v0 = unpackf2(acc[r][0]), v1 = unpackf2(acc[r][1]);
        float2 v2 = unpackf2(acc[r][2]), v3 = unpackf2(acc[r][3]);
        float* op = g_h + (size_t)(m0+i0+r)*DOUT_ + d0;
        *(float4*)(op)   = make_float4(v0.x,v0.y,v1.x,v1.y);
        *(float4*)(op+4) = make_float4(v2.x,v2.y,v3.x,v3.y);
    }
}

// ---------- w1 = h@a1, w2 = h@a2 (one warp per row) ----------
__global__ __launch_bounds__(256) void k_w(const float* __restrict__ a){
    int row  = blockIdx.x*8 + (threadIdx.x >> 5);
    int lane = threadIdx.x & 31;
    float4 h4 = *(const float4*)(g_h + (size_t)row*DOUT_ + lane*4);
    float4 a1 = *(const float4*)(a + lane*4);
    float4 a2 = *(const float4*)(a + DOUT_ + lane*4);
    float s1 = h4.x*a1.x + h4.y*a1.y + h4.z*a1.z + h4.w*a1.w;
    float s2 = h4.x*a2.x + h4.y*a2.y + h4.z*a2.z + h4.w*a2.w;
    #pragma unroll
    for (int off = 16; off; off >>= 1){
        s1 += __shfl_xor_sync(0xffffffffu, s1, off);
        s2 += __shfl_xor_sync(0xffffffffu, s2, off);
    }
    if (lane == 0){ g_w1[row] = s1; g_w2[row] = s2; }
}

// ---------- column sums S_j = sum_i masked G(w1_i + w2_j) ----------
__global__ __launch_bounds__(256) void k_colsum(){
    __shared__ float2 slut[LUT_N];
    __shared__ float  sred[256];
    for (int t = threadIdx.x; t < LUT_N; t += 256) slut[t] = g_lut[t];
    __syncthreads();
    int b  = blockIdx.x >> 5;
    int jb = blockIdx.x & 31;
    int jl = threadIdx.x & 127;
    int ih = threadIdx.x >> 7;
    int j  = jb*128 + jl;
    float w2 = g_w2[b*N_ + j];
    const unsigned* mbase = g_mask + (size_t)b*N_*NW_ + (j >> 5);
    const float* w1p = g_w1 + b*N_;
    int bit = j & 31;
    float acc = 0.f;
    int ibase = ih*2048;
    #pragma unroll 8
    for (int it = 0; it < 2048; it++){
        int i = ibase + it;
        unsigned word = mbase[(size_t)i*NW_];
        float s  = w1p[i] + w2;
        float tf = fminf(fmaxf(fmaf(s, LUT_INV, LUT_OFF), 0.f), MAXTF);
        int k = (int)tf;
        float fr = tf - (float)k;
        float2 lv = slut[k];
        float G = fmaf(fr, lv.y, lv.x);
        if ((word >> bit) & 1u) acc += G;
    }
    sred[threadIdx.x] = acc;
    __syncthreads();
    if (ih == 0){
        float S = acc + sred[threadIdx.x + 128];
        g_invS[b*N_ + j] = (S > 0.f) ? (1.0f/S) : (-1.0f/(float)N_);
    }
}

// ---------- out_raw = E @ (h * |invS|)  — fused, f32x2 ----------
__global__ __launch_bounds__(256) void k_passb(float* __restrict__ out){
    extern __shared__ float smem[];
    float2* slut = (float2*)smem;            // 4096 float2 = 32KB
    float2* Es   = (float2*)(smem + 8192);   // 64x32 duplicated pairs = 16KB
    float*  Hs   = smem + 8192 + 4096;       // 32x128 = 16KB
    for (int t = threadIdx.x; t < LUT_N; t += 256) slut[t] = g_lut[t];
    __syncthreads();   // slut must be complete before any E-tile generation
    int b  = blockIdx.x >> 6;
    int i0 = (blockIdx.x & 63) * 64;
    const float* w1p  = g_w1  + b*N_;
    const float* w2p  = g_w2  + b*N_;
    const float* invp = g_invS + b*N_;
    const float* hp   = g_h + (size_t)b*N_*DOUT_;
    const unsigned* mb = g_mask + (size_t)b*N_*NW_;
    int ig = threadIdx.x >> 5;   // 0..7  -> 8 rows each
    int dg = threadIdx.x & 31;   // 0..31 -> 4 cols each
    unsigned long long acc[8][2] = {};
    for (int kb = 0; kb < N_; kb += 32){
        {   // stage h' = h * |invS|
            int r = threadIdx.x >> 3;
            int c = (threadIdx.x & 7)*16;
            float inv = fabsf(invp[kb + r]);
            const float4* src = (const float4*)(hp + (size_t)(kb+r)*DOUT_ + c);
            float4* dst = (float4*)(Hs + r*DOUT_ + c);
            #pragma unroll
            for (int q = 0; q < 4; q++){
                float4 v = src[q];
                v.x *= inv; v.y *= inv; v.z *= inv; v.w *= inv;
                dst[q] = v;
            }
        }
        {   // generate E tile 64(i) x 32(j)
            unsigned jword = (unsigned)(kb >> 5);
            #pragma unroll
            for (int e = threadIdx.x; e < 64*32; e += 256){
                int ii = e >> 5, kk = e & 31;
                int i = i0 + ii, j = kb + kk;
                unsigned word = mb[(size_t)i*NW_ + jword];
                float inv = invp[j];
                float s  = w1p[i] + w2p[j];
                float tf = fminf(fmaxf(fmaf(s, LUT_INV, LUT_OFF), 0.f), MAXTF);
                int k = (int)tf;
                float fr = tf - (float)k;
                float2 lv = slut[k];
                float G = fmaf(fr, lv.y, lv.x);
                float wv = ((word >> kk) & 1u) ? G : 0.f;
                if (inv < 0.f) wv = 1.f;   // empty-column: uniform softmax
                Es[ii*32 + kk] = make_float2(wv, wv);
            }
        }
        __syncthreads();
        #pragma unroll 8
        for (int kk = 0; kk < 32; kk++){
            float4 hv = *(const float4*)(Hs + kk*DOUT_ + dg*4);
            unsigned long long hp0 = packf2(hv.x, hv.y);
            unsigned long long hp1 = packf2(hv.z, hv.w);
            #pragma unroll
            for (int r = 0; r < 8; r++){
                unsigned long long ev = *(const unsigned long long*)&Es[(ig*8+r)*32 + kk];
                acc[r][0] = ffma2(ev, hp0, acc[r][0]);
                acc[r][1] = ffma2(ev, hp1, acc[r][1]);
            }
        }
        __syncthreads();
    }
    #pragma unroll
    for (int r = 0; r < 8; r++){
        float2 v0 = unpackf2(acc[r][0]), v1 = unpackf2(acc[r][1]);
        *(float4*)(out + ((size_t)b*N_ + i0 + ig*8 + r)*DOUT_ + dg*4)
            = make_float4(v0.x, v0.y, v1.x, v1.y);
    }
}

// ---------- epilogue: gelu + partial norms (deterministic, no atomics) ----------
__global__ __launch_bounds__(256) void k_epi1(float* __restrict__ out){
    __shared__ float sred[256];
    int b  = blockIdx.x >> 5;
    int ib = blockIdx.x & 31;
    int d  = threadIdx.x & 127;
    int ih = threadIdx.x >> 7;
    float acc = 0.f;
    for (int r = 0; r < 64; r++){
        int i = ib*128 + ih*64 + r;
        size_t idx = ((size_t)b*N_ + i)*DOUT_ + d;
        float xv = out[idx];
        float g = 0.5f*xv*(1.0f + erff(xv*0.70710678118654752f));
        out[idx] = g;
        acc += g*g;
    }
    sred[threadIdx.x] = acc;
    __syncthreads();
    if (ih == 0) g_part[((size_t)b*32 + ib)*DOUT_ + d] = acc + sred[threadIdx.x + 128];
}

__global__ __launch_bounds__(256) void k_epi2(const float* __restrict__ bias, float* __restrict__ out){
    int b  = blockIdx.x >> 5;
    int ib = blockIdx.x & 31;
    int d  = threadIdx.x & 127;
    int ih = threadIdx.x >> 7;
    float n2 = 0.f;
    #pragma unroll
    for (int p = 0; p < 32; p++) n2 += g_part[((size_t)b*32 + p)*DOUT_ + d];
    float inv = 1.0f / fmaxf(sqrtf(n2), 1e-12f);
    float bs  = bias[d];
    for (int r = 0; r < 64; r++){
        int i = ib*128 + ih*64 + r;
        size_t idx = ((size_t)b*N_ + i)*DOUT_ + d;
        out[idx] = out[idx]*inv + bs;
    }
}

extern "C" void kernel_launch(void* const* d_in, const int* in_sizes, int n_in,
                              void* d_out, int out_size){
    const float* x    = (const float*)d_in[0];
    const int*   adj  = (const int*)  d_in[1];
    const float* w    = (const float*)d_in[2];
    const float* a    = (const float*)d_in[3];
    const float* bias = (const float*)d_in[4];
    float* out = (float*)d_out;

    cudaFuncSetAttribute((const void*)k_passb,
                         cudaFuncAttributeMaxDynamicSharedMemorySize, 65536);

    k_pack  <<<8192, 256>>>(adj);
    k_lut   <<<16,   256>>>();
    k_h     <<<128,  256>>>(x, w);
    k_w     <<<2048, 256>>>(a);
    k_colsum<<<128,  256>>>();
    k_passb <<<256,  256, 65536>>>(out);
    k_epi1  <<<128,  256>>>(out);
    k_epi2  <<<128,  256>>>(bias, out);
}

// round 4
// speedup vs baseline: 1.1587x; 1.1587x over previous
#include <cuda_runtime.h>
#include <math.h>

#define B_ 4
#define N_ 4096
#define DIN_ 256
#define DOUT_ 128
#define NW_ (N_/32)

#define LUT_N 4096
#define LUT_INV (36.571428571428571f)   /* 4096/112 */
#define LUT_OFF 2048.0f
#define MAXTF 4094.999f

__device__ float    g_h[B_*N_*DOUT_];
__device__ float    g_w1[B_*N_];
__device__ float    g_w2[B_*N_];
__device__ float    g_invS[B_*N_];
__device__ unsigned g_maskT[(size_t)B_*NW_*N_];   // [b][jw][i], i contiguous
__device__ float2   g_lut[LUT_N];
__device__ float    g_part[B_*32*DOUT_];

// ---------- packed fp32x2 helpers (sm_103a FFMA2) ----------
__device__ __forceinline__ unsigned long long packf2(float lo, float hi){
    unsigned long long r;
    asm("mov.b64 %0, {%1,%2};" : "=l"(r) : "f"(lo), "f"(hi));
    return r;
}
__device__ __forceinline__ float2 unpackf2(unsigned long long v){
    float2 r;
    asm("mov.b64 {%0,%1}, %2;" : "=f"(r.x), "=f"(r.y) : "l"(v));
    return r;
}
__device__ __forceinline__ unsigned long long ffma2(unsigned long long a, unsigned long long b, unsigned long long c){
    unsigned long long d;
    asm("fma.rn.f32x2 %0, %1, %2, %3;" : "=l"(d) : "l"(a), "l"(b), "l"(c));
    return d;
}

// ---------- pack adj -> TRANSPOSED bitmask: maskT[b][jw][i] ----------
__global__ __launch_bounds__(256) void k_pack(const int* __restrict__ adj){
    int wg   = (blockIdx.x*blockDim.x + threadIdx.x) >> 5;   // 0..65535
    int lane = threadIdx.x & 31;
    int b    = wg >> 14;           // 16384 warps per b
    int rem  = wg & 16383;
    int iblk = rem >> 7;           // 0..127
    int jw   = rem & 127;          // 0..127
    unsigned my = 0;
    #pragma unroll
    for (int w = 0; w < 32; w++){
        int row = iblk*32 + w;
        int v = adj[((size_t)(b*N_ + row))*N_ + jw*32 + lane];
        unsigned m = __ballot_sync(0xffffffffu, v > 0);
        if (lane == w) my = m;
    }
    g_maskT[((size_t)(b*NW_ + jw))*N_ + iblk*32 + lane] = my;
}

// ---------- LUT: G(s) = exp(gelu(s)) ----------
__global__ void k_lut(){
    int k = blockIdx.x*256 + threadIdx.x;
    if (k >= LUT_N) return;
    double step = 112.0/4096.0;
    double x0 = -56.0 + k*step;
    double x1 = x0 + step;
    double g0 = 0.5*x0*(1.0 + erf(x0*0.70710678118654752440));
    double g1 = 0.5*x1*(1.0 + erf(x1*0.70710678118654752440));
    float v0 = (float)exp(g0);
    float v1 = (float)exp(g1);
    g_lut[k] = make_float2(v0, v1 - v0);
}

// ---------- h = x @ W  (M=16384, N=128, K=256), f32x2 ----------
__global__ __launch_bounds__(256) void k_h(const float* __restrict__ x, const float* __restrict__ w){
    __shared__ float As[32*128];
    __shared__ float Bs[32*128];
    int m0 = blockIdx.x * 128;
    int ig = threadIdx.x >> 4;
    int dg = threadIdx.x & 15;
    int i0 = ig*8, d0 = dg*8;
    unsigned long long acc[8][4] = {};
    for (int kb = 0; kb < DIN_; kb += 32){
        __syncthreads();
        {
            int r  = threadIdx.x >> 1;
            int kh = (threadIdx.x & 1)*16;
            const float4* src = (const float4*)(x + (size_t)(m0+r)*DIN_ + kb + kh);
            #pragma unroll
            for (int q = 0; q < 4; q++){
                float4 v = src[q];
                int kc = kh + q*4;
                As[(kc+0)*128 + r] = v.x;
                As[(kc+1)*128 + r] = v.y;
                As[(kc+2)*128 + r] = v.z;
                As[(kc+3)*128 + r] = v.w;
            }
            int kk = threadIdx.x >> 3;
            int c  = (threadIdx.x & 7)*16;
            const float4* bsrc = (const float4*)(w + (size_t)(kb+kk)*DOUT_ + c);
            float4* bdst = (float4*)(Bs + kk*128 + c);
            #pragma unroll
            for (int q = 0; q < 4; q++) bdst[q] = bsrc[q];
        }
        __syncthreads();
        #pragma unroll 8
        for (int kk = 0; kk < 32; kk++){
            float4 a0 = *(const float4*)(As + kk*128 + i0);
            float4 a1 = *(const float4*)(As + kk*128 + i0 + 4);
            float4 b0 = *(const float4*)(Bs + kk*128 + d0);
            float4 b1 = *(const float4*)(Bs + kk*128 + d0 + 4);
            unsigned long long bp[4] = { packf2(b0.x,b0.y), packf2(b0.z,b0.w),
                                         packf2(b1.x,b1.y), packf2(b1.z,b1.w) };
            float aa[8] = {a0.x,a0.y,a0.z,a0.w,a1.x,a1.y,a1.z,a1.w};
            #pragma unroll
            for (int r = 0; r < 8; r++){
                unsigned long long ap = packf2(aa[r], aa[r]);
                #pragma unroll
                for (int p = 0; p < 4; p++) acc[r][p] = ffma2(ap, bp[p], acc[r][p]);
            }
        }
    }
    #pragma unroll
    for (int r = 0; r < 8; r++){
        float2 v0 = unpackf2(acc[r][0]), v1 = unpackf2(acc[r][1]);
        float2 v2 = unpackf2(acc[r][2]), v3 = unpackf2(acc[r][3]);
        float* op = g_h + (size_t)(m0+i0+r)*DOUT_ + d0;
        *(float4*)(op)   = make_float4(v0.x,v0.y,v1.x,v1.y);
        *(float4*)(op+4) = make_float4(v2.x,v2.y,v3.x,v3.y);
    }
}

// ---------- w1 = h@a1, w2 = h@a2 ----------
__global__ __launch_bounds__(256) void k_w(const float* __restrict__ a){
    int row  = blockIdx.x*8 + (threadIdx.x >> 5);
    int lane = threadIdx.x & 31;
    float4 h4 = *(const float4*)(g_h + (size_t)row*DOUT_ + lane*4);
    float4 a1 = *(const float4*)(a + lane*4);
    float4 a2 = *(const float4*)(a + DOUT_ + lane*4);
    float s1 = h4.x*a1.x + h4.y*a1.y + h4.z*a1.z + h4.w*a1.w;
    float s2 = h4.x*a2.x + h4.y*a2.y + h4.z*a2.z + h4.w*a2.w;
    #pragma unroll
    for (int off = 16; off; off >>= 1){
        s1 += __shfl_xor_sync(0xffffffffu, s1, off);
        s2 += __shfl_xor_sync(0xffffffffu, s2, off);
    }
    if (lane == 0){ g_w1[row] = s1; g_w2[row] = s2; }
}

// ---------- column sums S_j over i (contiguous mask stream) ----------
__global__ __launch_bounds__(256) void k_colsum(){
    __shared__ float2 slut[LUT_N];
    __shared__ float  sred[256];
    for (int t = threadIdx.x; t < LUT_N; t += 256) slut[t] = g_lut[t];
    __syncthreads();
    int b  = blockIdx.x >> 6;          // 4 b x 64 j-blocks
    int jb = blockIdx.x & 63;
    int jl = threadIdx.x & 63;
    int ih = threadIdx.x >> 6;         // 0..3, i split 4 x 1024
    int j  = jb*64 + jl;
    float w2 = g_w2[b*N_ + j];
    const unsigned* mrow = g_maskT + ((size_t)(b*NW_ + (j >> 5)))*N_;
    const float* w1p = g_w1 + b*N_;
    int bit = j & 31;
    float acc = 0.f;
    int ibase = ih*1024;
    #pragma unroll 8
    for (int it = 0; it < 1024; it++){
        int i = ibase + it;
        unsigned word = mrow[i];
        float s  = w1p[i] + w2;
        float tf = fminf(fmaxf(fmaf(s, LUT_INV, LUT_OFF), 0.f), MAXTF);
        int k = (int)tf;
        float fr = tf - (float)k;
        float2 lv = slut[k];
        float G = fmaf(fr, lv.y, lv.x);
        if ((word >> bit) & 1u) acc += G;
    }
    sred[threadIdx.x] = acc;
    __syncthreads();
    if (ih == 0){
        float S = acc + sred[threadIdx.x + 64] + sred[threadIdx.x + 128] + sred[threadIdx.x + 192];
        g_invS[b*N_ + j] = (S > 0.f) ? (1.0f/S) : (-1.0f/(float)N_);
    }
}

// ---------- out_raw = E @ (h * |invS|)  — fused, f32x2, broadcast E loads ----------
__global__ __launch_bounds__(256) void k_passb(float* __restrict__ out){
    extern __shared__ float smem[];
    float2* slut = (float2*)smem;                  // 8192 floats = 32KB
    float2* Es   = (float2*)(smem + 8192);         // [kk][ii] 32x64 float2 = 16KB
    float*  Hs   = smem + 8192 + 4096;             // 32x128 = 16KB
    for (int t = threadIdx.x; t < LUT_N; t += 256) slut[t] = g_lut[t];
    int b  = blockIdx.x >> 6;
    int i0 = (blockIdx.x & 63) * 64;
    const float* w2p  = g_w2  + b*N_;
    const float* invp = g_invS + b*N_;
    const float* hp   = g_h + (size_t)b*N_*DOUT_;
    int tid = threadIdx.x;
    // E-gen ownership: fixed row ii per thread, 8 kk values (kkbase + 4t)
    int ii     = tid & 63;
    int kkbase = tid >> 6;         // 0..3
    float w1i  = g_w1[b*N_ + i0 + ii];
    const unsigned* mcol = g_maskT + (size_t)b*NW_*N_ + (i0 + ii);  // + jw*N_ per tile
    // FMA ownership
    int ig = tid >> 5;             // 0..7 -> rows ig*8..+7
    int dg = tid & 31;             // cols dg*4..+3
    unsigned long long acc[8][2] = {};
    __syncthreads();               // slut ready
    for (int kb = 0; kb < N_; kb += 32){
        {   // stage h' = h * |invS| : 32 rows x 128
            int r = tid >> 3;
            int c = (tid & 7)*16;
            float inv = fabsf(invp[kb + r]);
            const float4* src = (const float4*)(hp + (size_t)(kb+r)*DOUT_ + c);
            float4* dst = (float4*)(Hs + r*DOUT_ + c);
            #pragma unroll
            for (int q = 0; q < 4; q++){
                float4 v = src[q];
                v.x *= inv; v.y *= inv; v.z *= inv; v.w *= inv;
                dst[q] = v;
            }
        }
        {   // generate E tile: this thread's row ii, kk = kkbase+4t
            unsigned word = mcol[(size_t)(kb >> 5) * N_];   // coalesced across lanes
            #pragma unroll
            for (int t = 0; t < 8; t++){
                int kk = kkbase + 4*t;
                int j  = kb + kk;
                float w2  = w2p[j];    // uniform per warp -> broadcast
                float inv = invp[j];
                float s  = w1i + w2;
                float tf = fminf(fmaxf(fmaf(s, LUT_INV, LUT_OFF), 0.f), MAXTF);
                int k = (int)tf;
                float fr = tf - (float)k;
                float2 lv = slut[k];
                float G = fmaf(fr, lv.y, lv.x);
                float wv = ((word >> kk) & 1u) ? G : 0.f;
                if (inv < 0.f) wv = 1.f;   // empty column: uniform softmax
                Es[kk*64 + ii] = make_float2(wv, wv);
            }
        }
        __syncthreads();
        #pragma unroll 8
        for (int kk = 0; kk < 32; kk++){
            float4 hv = *(const float4*)(Hs + kk*DOUT_ + dg*4);
            unsigned long long hp0 = packf2(hv.x, hv.y);
            unsigned long long hp1 = packf2(hv.z, hv.w);
            const ulonglong2* ep = (const ulonglong2*)(Es + kk*64 + ig*8);  // broadcast
            #pragma unroll
            for (int q = 0; q < 4; q++){
                ulonglong2 ev = ep[q];       // rows ig*8+2q, ig*8+2q+1 (duplicated pairs)
                acc[2*q  ][0] = ffma2(ev.x, hp0, acc[2*q  ][0]);
                acc[2*q  ][1] = ffma2(ev.x, hp1, acc[2*q  ][1]);
                acc[2*q+1][0] = ffma2(ev.y, hp0, acc[2*q+1][0]);
                acc[2*q+1][1] = ffma2(ev.y, hp1, acc[2*q+1][1]);
            }
        }
        __syncthreads();
    }
    #pragma unroll
    for (int r = 0; r < 8; r++){
        float2 v0 = unpackf2(acc[r][0]), v1 = unpackf2(acc[r][1]);
        *(float4*)(out + ((size_t)b*N_ + i0 + ig*8 + r)*DOUT_ + dg*4)
            = make_float4(v0.x, v0.y, v1.x, v1.y);
    }
}

// ---------- epilogue: gelu + deterministic two-stage norm ----------
__global__ __launch_bounds__(256) void k_epi1(float* __restrict__ out){
    __shared__ float sred[256];
    int b  = blockIdx.x >> 5;
    int ib = blockIdx.x & 31;
    int d  = threadIdx.x & 127;
    int ih = threadIdx.x >> 7;
    float acc = 0.f;
    for (int r = 0; r < 64; r++){
        int i = ib*128 + ih*64 + r;
        size_t idx = ((size_t)b*N_ + i)*DOUT_ + d;
        float xv = out[idx];
        float g = 0.5f*xv*(1.0f + erff(xv*0.70710678118654752f));
        out[idx] = g;
        acc += g*g;
    }
    sred[threadIdx.x] = acc;
    __syncthreads();
    if (ih == 0) g_part[((size_t)b*32 + ib)*DOUT_ + d] = acc + sred[threadIdx.x + 128];
}

__global__ __launch_bounds__(256) void k_epi2(const float* __restrict__ bias, float* __restrict__ out){
    int b  = blockIdx.x >> 5;
    int ib = blockIdx.x & 31;
    int d  = threadIdx.x & 127;
    int ih = threadIdx.x >> 7;
    float n2 = 0.f;
    #pragma unroll
    for (int p = 0; p < 32; p++) n2 += g_part[((size_t)b*32 + p)*DOUT_ + d];
    float inv = 1.0f / fmaxf(sqrtf(n2), 1e-12f);
    float bs  = bias[d];
    for (int r = 0; r < 64; r++){
        int i = ib*128 + ih*64 + r;
        size_t idx = ((size_t)b*N_ + i)*DOUT_ + d;
        out[idx] = out[idx]*inv + bs;
    }
}

extern "C" void kernel_launch(void* const* d_in, const int* in_sizes, int n_in,
                              void* d_out, int out_size){
    const float* x    = (const float*)d_in[0];
    const int*   adj  = (const int*)  d_in[1];
    const float* w    = (const float*)d_in[2];
    const float* a    = (const float*)d_in[3];
    const float* bias = (const float*)d_in[4];
    float* out = (float*)d_out;

    cudaFuncSetAttribute((const void*)k_passb,
                         cudaFuncAttributeMaxDynamicSharedMemorySize, 65536);

    k_pack  <<<8192, 256>>>(adj);
    k_lut   <<<16,   256>>>();
    k_h     <<<128,  256>>>(x, w);
    k_w     <<<2048, 256>>>(a);
    k_colsum<<<256,  256>>>();
    k_passb <<<256,  256, 65536>>>(out);
    k_epi1  <<<128,  256>>>(out);
    k_epi2  <<<128,  256>>>(bias, out);
}

// round 11
// speedup vs baseline: 1.9014x; 1.6410x over previous
#include <cuda_runtime.h>
#include <cuda_bf16.h>
#include <math.h>
#include <stdint.h>

#define B_ 4
#define N_ 4096
#define DIN_ 256
#define DOUT_ 128
#define NW_ (N_/32)

#define LUT_N 4096
#define LUT_INV (36.571428571428571f)   /* 4096/112 */
#define LUT_OFF 2048.0f
#define MAXTF 4094.999f

__device__ float    g_h[B_*N_*DOUT_];
__device__ float    g_w1[B_*N_];
__device__ float    g_w2[B_*N_];
__device__ float    g_invS[B_*N_];
__device__ unsigned g_maskT[(size_t)B_*NW_*N_];   // [b][jw][i], i contiguous
__device__ float2   g_lut[LUT_N];
__device__ float    g_part[B_*32*DOUT_];
__device__ unsigned short g_hThi[(size_t)B_*DOUT_*N_];  // h' transposed, bf16 hi  [b][d][j]
__device__ unsigned short g_hTlo[(size_t)B_*DOUT_*N_];  // h' transposed, bf16 lo

// ---------- packed fp32x2 helpers (sm_103a FFMA2) ----------
__device__ __forceinline__ unsigned long long packf2(float lo, float hi){
    unsigned long long r;
    asm("mov.b64 %0, {%1,%2};" : "=l"(r) : "f"(lo), "f"(hi));
    return r;
}
__device__ __forceinline__ float2 unpackf2(unsigned long long v){
    float2 r;
    asm("mov.b64 {%0,%1}, %2;" : "=f"(r.x), "=f"(r.y) : "l"(v));
    return r;
}
__device__ __forceinline__ unsigned long long ffma2(unsigned long long a, unsigned long long b, unsigned long long c){
    unsigned long long d;
    asm("fma.rn.f32x2 %0, %1, %2, %3;" : "=l"(d) : "l"(a), "l"(b), "l"(c));
    return d;
}

// ---------- mma / ldmatrix helpers (standard PTX, works at sm_103 base target) ----------
__device__ __forceinline__ uint32_t smem_u32(const void* p){
    uint32_t a;
    asm("{ .reg .u64 t; cvta.to.shared.u64 t, %1; cvt.u32.u64 %0, t; }" : "=r"(a) : "l"(p));
    return a;
}
__device__ __forceinline__ void ldsm_x4(uint32_t* r, uint32_t addr){
    asm volatile("ldmatrix.sync.aligned.m8n8.x4.shared.b16 {%0,%1,%2,%3}, [%4];"
                 : "=r"(r[0]), "=r"(r[1]), "=r"(r[2]), "=r"(r[3]) : "r"(addr));
}
__device__ __forceinline__ void mma16816(float* d, const uint32_t* a, const uint32_t* b){
    asm volatile("mma.sync.aligned.m16n8k16.row.col.f32.bf16.bf16.f32 "
                 "{%0,%1,%2,%3},{%4,%5,%6,%7},{%8,%9},{%0,%1,%2,%3};"
                 : "+f"(d[0]), "+f"(d[1]), "+f"(d[2]), "+f"(d[3])
                 : "r"(a[0]), "r"(a[1]), "r"(a[2]), "r"(a[3]), "r"(b[0]), "r"(b[1]));
}

__device__ __forceinline__ void bf16split(float v, unsigned short &hi, unsigned short &lo){
    __nv_bfloat16 h = __float2bfloat16_rn(v);
    float r = v - __bfloat162float(h);
    __nv_bfloat16 l = __float2bfloat16_rn(r);
    hi = __bfloat16_as_ushort(h);
    lo = __bfloat16_as_ushort(l);
}

// ---------- pack adj -> TRANSPOSED bitmask ----------
__global__ __launch_bounds__(256) void k_pack(const int* __restrict__ adj){
    int wg   = (blockIdx.x*blockDim.x + threadIdx.x) >> 5;
    int lane = threadIdx.x & 31;
    int b    = wg >> 14;
    int rem  = wg & 16383;
    int iblk = rem >> 7;
    int jw   = rem & 127;
    unsigned my = 0;
    #pragma unroll
    for (int w = 0; w < 32; w++){
        int row = iblk*32 + w;
        int v = adj[((size_t)(b*N_ + row))*N_ + jw*32 + lane];
        unsigned m = __ballot_sync(0xffffffffu, v > 0);
        if (lane == w) my = m;
    }
    g_maskT[((size_t)(b*NW_ + jw))*N_ + iblk*32 + lane] = my;
}

// ---------- LUT: G(s) = exp(gelu(s)) ----------
__global__ void k_lut(){
    int k = blockIdx.x*256 + threadIdx.x;
    if (k >= LUT_N) return;
    double step = 112.0/4096.0;
    double x0 = -56.0 + k*step;
    double x1 = x0 + step;
    double g0 = 0.5*x0*(1.0 + erf(x0*0.70710678118654752440));
    double g1 = 0.5*x1*(1.0 + erf(x1*0.70710678118654752440));
    float v0 = (float)exp(g0);
    float v1 = (float)exp(g1);
    g_lut[k] = make_float2(v0, v1 - v0);
}

// ---------- h = x @ W  (f32x2 SIMT) ----------
__global__ __launch_bounds__(256) void k_h(const float* __restrict__ x, const float* __restrict__ w){
    __shared__ float As[32*128];
    __shared__ float Bs[32*128];
    int m0 = blockIdx.x * 128;
    int ig = threadIdx.x >> 4;
    int dg = threadIdx.x & 15;
    int i0 = ig*8, d0 = dg*8;
    unsigned long long acc[8][4] = {};
    for (int kb = 0; kb < DIN_; kb += 32){
        __syncthreads();
        {
            int r  = threadIdx.x >> 1;
            int kh = (threadIdx.x & 1)*16;
            const float4* src = (const float4*)(x + (size_t)(m0+r)*DIN_ + kb + kh);
            #pragma unroll
            for (int q = 0; q < 4; q++){
                float4 v = src[q];
                int kc = kh + q*4;
                As[(kc+0)*128 + r] = v.x;
                As[(kc+1)*128 + r] = v.y;
                As[(kc+2)*128 + r] = v.z;
                As[(kc+3)*128 + r] = v.w;
            }
            int kk = threadIdx.x >> 3;
            int c  = (threadIdx.x & 7)*16;
            const float4* bsrc = (const float4*)(w + (size_t)(kb+kk)*DOUT_ + c);
            float4* bdst = (float4*)(Bs + kk*128 + c);
            #pragma unroll
            for (int q = 0; q < 4; q++) bdst[q] = bsrc[q];
        }
        __syncthreads();
        #pragma unroll 8
        for (int kk = 0; kk < 32; kk++){
            float4 a0 = *(const float4*)(As + kk*128 + i0);
            float4 a1 = *(const float4*)(As + kk*128 + i0 + 4);
            float4 b0 = *(const float4*)(Bs + kk*128 + d0);
            float4 b1 = *(const float4*)(Bs + kk*128 + d0 + 4);
            unsigned long long bp[4] = { packf2(b0.x,b0.y), packf2(b0.z,b0.w),
                                         packf2(b1.x,b1.y), packf2(b1.z,b1.w) };
            float aa[8] = {a0.x,a0.y,a0.z,a0.w,a1.x,a1.y,a1.z,a1.w};
            #pragma unroll
            for (int r = 0; r < 8; r++){
                unsigned long long ap = packf2(aa[r], aa[r]);
                #pragma unroll
                for (int p = 0; p < 4; p++) acc[r][p] = ffma2(ap, bp[p], acc[r][p]);
            }
        }
    }
    #pragma unroll
    for (int r = 0; r < 8; r++){
        float2 v0 = unpackf2(acc[r][0]), v1 = unpackf2(acc[r][1]);
        float2 v2 = unpackf2(acc[r][2]), v3 = unpackf2(acc[r][3]);
        float* op = g_h + (size_t)(m0+i0+r)*DOUT_ + d0;
        *(float4*)(op)   = make_float4(v0.x,v0.y,v1.x,v1.y);
        *(float4*)(op+4) = make_float4(v2.x,v2.y,v3.x,v3.y);
    }
}

// ---------- w1 = h@a1, w2 = h@a2 ----------
__global__ __launch_bounds__(256) void k_w(const float* __restrict__ a){
    int row  = blockIdx.x*8 + (threadIdx.x >> 5);
    int lane = threadIdx.x & 31;
    float4 h4 = *(const float4*)(g_h + (size_t)row*DOUT_ + lane*4);
    float4 a1 = *(const float4*)(a + lane*4);
    float4 a2 = *(const float4*)(a + DOUT_ + lane*4);
    float s1 = h4.x*a1.x + h4.y*a1.y + h4.z*a1.z + h4.w*a1.w;
    float s2 = h4.x*a2.x + h4.y*a2.y + h4.z*a2.z + h4.w*a2.w;
    #pragma unroll
    for (int off = 16; off; off >>= 1){
        s1 += __shfl_xor_sync(0xffffffffu, s1, off);
        s2 += __shfl_xor_sync(0xffffffffu, s2, off);
    }
    if (lane == 0){ g_w1[row] = s1; g_w2[row] = s2; }
}

// ---------- column sums ----------
__global__ __launch_bounds__(256) void k_colsum(){
    __shared__ float2 slut[LUT_N];
    __shared__ float  sred[256];
    for (int t = threadIdx.x; t < LUT_N; t += 256) slut[t] = g_lut[t];
    __syncthreads();
    int b  = blockIdx.x >> 6;
    int jb = blockIdx.x & 63;
    int jl = threadIdx.x & 63;
    int ih = threadIdx.x >> 6;
    int j  = jb*64 + jl;
    float w2 = g_w2[b*N_ + j];
    const unsigned* mrow = g_maskT + ((size_t)(b*NW_ + (j >> 5)))*N_;
    const float* w1p = g_w1 + b*N_;
    int bit = j & 31;
    float acc = 0.f;
    int ibase = ih*1024;
    #pragma unroll 8
    for (int it = 0; it < 1024; it++){
        int i = ibase + it;
        unsigned word = mrow[i];
        float s  = w1p[i] + w2;
        float tf = fminf(fmaxf(fmaf(s, LUT_INV, LUT_OFF), 0.f), MAXTF);
        int k = (int)tf;
        float fr = tf - (float)k;
        float2 lv = slut[k];
        float G = fmaf(fr, lv.y, lv.x);
        if ((word >> bit) & 1u) acc += G;
    }
    sred[threadIdx.x] = acc;
    __syncthreads();
    if (ih == 0){
        float S = acc + sred[threadIdx.x + 64] + sred[threadIdx.x + 128] + sred[threadIdx.x + 192];
        g_invS[b*N_ + j] = (S > 0.f) ? (1.0f/S) : (-1.0f/(float)N_);
    }
}

// ---------- h' = h*|invS| -> transposed bf16 split [b][d][j] ----------
__global__ __launch_bounds__(256) void k_hsplit(){
    int g  = blockIdx.x*256 + threadIdx.x;       // 512 blocks
    int d  = g & 127;
    int jc = (g >> 7) & 255;                      // j chunk of 16
    int b  = g >> 15;
    unsigned hi4[8], lo4[8];
    #pragma unroll
    for (int u = 0; u < 16; u += 2){
        int j0 = jc*16 + u;
        float inv0 = fabsf(g_invS[b*N_ + j0]);
        float inv1 = fabsf(g_invS[b*N_ + j0 + 1]);
        float v0 = g_h[((size_t)b*N_ + j0)*DOUT_ + d] * inv0;
        float v1 = g_h[((size_t)b*N_ + j0 + 1)*DOUT_ + d] * inv1;
        unsigned short h0,l0,h1,l1;
        bf16split(v0, h0, l0);
        bf16split(v1, h1, l1);
        hi4[u>>1] = (unsigned)h0 | ((unsigned)h1 << 16);
        lo4[u>>1] = (unsigned)l0 | ((unsigned)l1 << 16);
    }
    size_t base = ((size_t)(b*DOUT_ + d))*N_ + jc*16;
    *(uint4*)(&g_hThi[base])     = make_uint4(hi4[0],hi4[1],hi4[2],hi4[3]);
    *(uint4*)(&g_hThi[base + 8]) = make_uint4(hi4[4],hi4[5],hi4[6],hi4[7]);
    *(uint4*)(&g_hTlo[base])     = make_uint4(lo4[0],lo4[1],lo4[2],lo4[3]);
    *(uint4*)(&g_hTlo[base + 8]) = make_uint4(lo4[4],lo4[5],lo4[6],lo4[7]);
}

// ---------- out_raw = E @ h'  via mma.sync bf16 3-term split ----------
// SMEM: LUT 32KB; A/B tiles with 80B row stride (conflict-free ldmatrix)
#define SMB_LUT 0
#define SMB_AHI 32768
#define SMB_ALO 43008
#define SMB_BHI 53248
#define SMB_BLO 63488
#define SMB_TOT 73728
#define RSTRIDE 80

__global__ __launch_bounds__(256) void k_passb_mma(float* __restrict__ out){
    extern __shared__ char smem[];
    uint32_t sb = smem_u32(smem);
    float2* slut = (float2*)(smem + SMB_LUT);
    int tid = threadIdx.x;
    for (int t = tid; t < LUT_N; t += 256) slut[t] = g_lut[t];

    int b  = blockIdx.x >> 5;          // 128 blocks: 4 b x 32 i-tiles of 128
    int i0 = (blockIdx.x & 31) * 128;

    // E-gen ownership: row ii, j-half jh (16 j's of the 32-wide k-tile)
    int ii = tid & 127;
    int jh = tid >> 7;
    float w1i = g_w1[b*N_ + i0 + ii];
    const unsigned* mbase = g_maskT + (size_t)b*NW_*N_ + (i0 + ii);
    const float* w2p  = g_w2   + b*N_;
    const float* invp = g_invS + b*N_;
    // B staging ownership
    int srow  = tid >> 1;
    int shalf = tid & 1;
    const unsigned short* hThi = g_hThi + (size_t)b*DOUT_*N_;
    const unsigned short* hTlo = g_hTlo + (size_t)b*DOUT_*N_;
    // mma ownership: 4(m) x 2(n) warps, warp tile 32m x 64n
    int wid = tid >> 5, lane = tid & 31;
    int m0 = (wid & 3) * 32;
    int n0 = (wid >> 2) * 64;
    uint32_t aoff = (uint32_t)((m0 + (lane & 15))*RSTRIDE + ((lane >> 4) << 4));
    uint32_t boff = (uint32_t)((n0 + (lane & 7) + ((lane >> 4) << 3))*RSTRIDE + (((lane >> 3) & 1) << 4));

    float acc[2][8][4] = {};
    __syncthreads();    // LUT ready

    for (int t = 0; t < 128; t++){
        int j0 = t*32;
        {   // stage B: 128 d-rows x 32 j (hi & lo)
            const uint4* sh = (const uint4*)(hThi + (size_t)srow*N_ + j0 + shalf*16);
            const uint4* sl = (const uint4*)(hTlo + (size_t)srow*N_ + j0 + shalf*16);
            uint4 h0 = sh[0], h1 = sh[1];
            uint4 l0 = sl[0], l1 = sl[1];
            uint4* dh = (uint4*)(smem + SMB_BHI + srow*RSTRIDE + shalf*32);
            uint4* dl = (uint4*)(smem + SMB_BLO + srow*RSTRIDE + shalf*32);
            dh[0] = h0; dh[1] = h1;
            dl[0] = l0; dl[1] = l1;
        }
        {   // E-gen: row ii, 16 j's
            unsigned word = mbase[(size_t)t * N_];
            int jbase = j0 + jh*16;
            uint32_t ahi[8], alo[8];
            #pragma unroll
            for (int q = 0; q < 4; q++){
                float4 w2v  = *(const float4*)(w2p  + jbase + q*4);
                float4 invv = *(const float4*)(invp + jbase + q*4);
                float w2a[4] = {w2v.x, w2v.y, w2v.z, w2v.w};
                float iva[4] = {invv.x, invv.y, invv.z, invv.w};
                unsigned short hh[4], ll[4];
                #pragma unroll
                for (int r = 0; r < 4; r++){
                    float s  = w1i + w2a[r];
                    float tf = fminf(fmaxf(fmaf(s, LUT_INV, LUT_OFF), 0.f), MAXTF);
                    int k = (int)tf;
                    float fr = tf - (float)k;
                    float2 lv = slut[k];
                    float G = fmaf(fr, lv.y, lv.x);
                    float v = ((word >> (jh*16 + q*4 + r)) & 1u) ? G : 0.f;
                    if (iva[r] < 0.f) v = 1.f;   // empty column: uniform softmax
                    bf16split(v, hh[r], ll[r]);
                }
                ahi[q*2]   = (unsigned)hh[0] | ((unsigned)hh[1] << 16);
                ahi[q*2+1] = (unsigned)hh[2] | ((unsigned)hh[3] << 16);
                alo[q*2]   = (unsigned)ll[0] | ((unsigned)ll[1] << 16);
                alo[q*2+1] = (unsigned)ll[2] | ((unsigned)ll[3] << 16);
            }
            uint4* dh = (uint4*)(smem + SMB_AHI + ii*RSTRIDE + jh*32);
            uint4* dl = (uint4*)(smem + SMB_ALO + ii*RSTRIDE + jh*32);
            dh[0] = make_uint4(ahi[0],ahi[1],ahi[2],ahi[3]);
            dh[1] = make_uint4(ahi[4],ahi[5],ahi[6],ahi[7]);
            dl[0] = make_uint4(alo[0],alo[1],alo[2],alo[3]);
            dl[1] = make_uint4(alo[4],alo[5],alo[6],alo[7]);
        }
        __syncthreads();
        #pragma unroll
        for (int kk = 0; kk < 2; kk++){
            uint32_t ko = kk*32;
            uint32_t ah0[4], ah1[4], al0[4], al1[4];
            ldsm_x4(ah0, sb + SMB_AHI + aoff + ko);
            ldsm_x4(ah1, sb + SMB_AHI + aoff + 16*RSTRIDE + ko);
            ldsm_x4(al0, sb + SMB_ALO + aoff + ko);
            ldsm_x4(al1, sb + SMB_ALO + aoff + 16*RSTRIDE + ko);
            uint32_t bh[16], bl[16];
            #pragma unroll
            for (int nb = 0; nb < 4; nb++){
                ldsm_x4(&bh[nb*4], sb + SMB_BHI + boff + nb*16*RSTRIDE + ko);
                ldsm_x4(&bl[nb*4], sb + SMB_BLO + boff + nb*16*RSTRIDE + ko);
            }
            #pragma unroll
            for (int nf = 0; nf < 8; nf++){
                mma16816(acc[0][nf], ah0, &bh[nf*2]);
                mma16816(acc[1][nf], ah1, &bh[nf*2]);
                mma16816(acc[0][nf], ah0, &bl[nf*2]);
                mma16816(acc[1][nf], ah1, &bl[nf*2]);
                mma16816(acc[0][nf], al0, &bh[nf*2]);
                mma16816(acc[1][nf], al1, &bh[nf*2]);
            }
        }
        __syncthreads();
    }

    // epilogue: direct register -> gmem (mma D fragment mapping)
    int g  = lane >> 2;
    int tq = lane & 3;
    #pragma unroll
    for (int mf = 0; mf < 2; mf++){
        #pragma unroll
        for (int nf = 0; nf < 8; nf++){
            int row = i0 + m0 + mf*16 + g;
            int col = n0 + nf*8 + tq*2;
            float2 v0 = make_float2(acc[mf][nf][0], acc[mf][nf][1]);
            float2 v1 = make_float2(acc[mf][nf][2], acc[mf][nf][3]);
            *(float2*)(out + ((size_t)b*N_ + row)*DOUT_ + col)     = v0;
            *(float2*)(out + ((size_t)b*N_ + row + 8)*DOUT_ + col) = v1;
        }
    }
}

// ---------- epilogue: gelu + deterministic two-stage norm ----------
__global__ __launch_bounds__(256) void k_epi1(float* __restrict__ out){
    __shared__ float sred[256];
    int b  = blockIdx.x >> 5;
    int ib = blockIdx.x & 31;
    int d  = threadIdx.x & 127;
    int ih = threadIdx.x >> 7;
    float acc = 0.f;
    for (int r = 0; r < 64; r++){
        int i = ib*128 + ih*64 + r;
        size_t idx = ((size_t)b*N_ + i)*DOUT_ + d;
        float xv = out[idx];
        float g = 0.5f*xv*(1.0f + erff(xv*0.70710678118654752f));
        out[idx] = g;
        acc += g*g;
    }
    sred[threadIdx.x] = acc;
    __syncthreads();
    if (ih == 0) g_part[((size_t)b*32 + ib)*DOUT_ + d] = acc + sred[threadIdx.x + 128];
}

__global__ __launch_bounds__(256) void k_epi2(const float* __restrict__ bias, float* __restrict__ out){
    int b  = blockIdx.x >> 5;
    int ib = blockIdx.x & 31;
    int d  = threadIdx.x & 127;
    int ih = threadIdx.x >> 7;
    float n2 = 0.f;
    #pragma unroll
    for (int p = 0; p < 32; p++) n2 += g_part[((size_t)b*32 + p)*DOUT_ + d];
    float inv = 1.0f / fmaxf(sqrtf(n2), 1e-12f);
    float bs  = bias[d];
    for (int r = 0; r < 64; r++){
        int i = ib*128 + ih*64 + r;
        size_t idx = ((size_t)b*N_ + i)*DOUT_ + d;
        out[idx] = out[idx]*inv + bs;
    }
}

extern "C" void kernel_launch(void* const* d_in, const int* in_sizes, int n_in,
                              void* d_out, int out_size){
    const float* x    = (const float*)d_in[0];
    const int*   adj  = (const int*)  d_in[1];
    const float* w    = (const float*)d_in[2];
    const float* a    = (const float*)d_in[3];
    const float* bias = (const float*)d_in[4];
    float* out = (float*)d_out;

    cudaFuncSetAttribute((const void*)k_passb_mma,
                         cudaFuncAttributeMaxDynamicSharedMemorySize, SMB_TOT);

    k_pack     <<<8192, 256>>>(adj);
    k_lut      <<<16,   256>>>();
    k_h        <<<128,  256>>>(x, w);
    k_w        <<<2048, 256>>>(a);
    k_colsum   <<<256,  256>>>();
    k_hsplit   <<<512,  256>>>();
    k_passb_mma<<<128,  256, SMB_TOT>>>(out);
    k_epi1     <<<128,  256>>>(out);
    k_epi2     <<<128,  256>>>(bias, out);
}